// round 16
// baseline (speedup 1.0000x reference)
#include <cuda_runtime.h>

// SpatialWeightsEsDot on GB300.
//   phi = w_phi @ u (1x1 conv), layout [b][c][y][x]
//   M_{dy,dx}[b][y][x] = sum_c phi[b,c,y,x]*phi[b,c,y+dy,x+dx]  (zero outside image)
//   score[p,d] = 1[p+d in image] * sum_{e in 3x3} M_d[p+e]
//   out = softmax over the 49 offsets -> [2,128,128,1,49]

#define HH 128
#define WW 128
#define CC 64

__device__ float g_phi[2 * CC * HH * WW];     // [b][c][y][x]
__device__ float g_M[49 * 2 * HH * WW];       // [off][b][y][x], off=(dy+3)*7+(dx+3)

typedef unsigned long long u64;

__device__ __forceinline__ void ffma2(u64& d, u64 a, u64 b) {
    asm("fma.rn.f32x2 %0, %1, %2, %3;" : "=l"(d) : "l"(a), "l"(b), "l"(d));
}
__device__ __forceinline__ u64 dup2(float v) {
    u64 d; asm("mov.b64 %0, {%1, %1};" : "=l"(d) : "f"(v)); return d;
}

// ---------------------------------------------------------------------------
// K1: phi v9. Warp supply is the confirmed binder (R15): 2x the warps again.
// Thread = 2 px x 4 outs -> 8192 warps (55/SM demand). Pre-dup {w,w} pairs in
// smem so k-body = 1 LDS.64 (u) + 2 LDS.128 (w pairs, broadcast) + 4 FFMA2 =
// 7 instr / 8 MACs, FFMA2 consumes LDS directly (no dup-mov hop).
// Block 256 = 64 px x 32 outs; grid (512 px-tiles, 2 out-halves).
// ---------------------------------------------------------------------------
__global__ void __launch_bounds__(256, 6)
phi_kernel(const float* __restrict__ u, const float* __restrict__ w) {
    __shared__ float s_u[CC * 64];             // [k][px] 16KB
    __shared__ u64 s_w2[CC * 32];              // [k][o] dup pairs 16KB
    int tid  = threadIdx.x;
    int p0   = blockIdx.x * 64;
    int b    = p0 >> 14;
    int pb   = p0 & 16383;
    int half = blockIdx.y;                     // outputs half*32 .. half*32+31

    for (int i = tid; i < CC * 32; i += 256) {
        int k = i >> 5, o = i & 31;
        s_w2[i] = dup2(w[(half * 32 + o) * CC + k]);
    }
    const float* ub = u + (size_t)b * CC * 16384 + pb;
    for (int i = tid; i < 1024; i += 256) {    // 64k x 16 float4
        int k = i >> 4, p4 = (i & 15) << 2;
        *(float4*)&s_u[k * 64 + p4] = *(const float4*)(ub + (size_t)k * 16384 + p4);
    }
    __syncthreads();

    int lane = tid & 31;
    int wrp  = tid >> 5;                       // 0..7 -> 4 outs
    int px   = lane << 1;                      // 2 px per thread
    int o0   = wrp << 2;

    u64 acc[4] = {0ull, 0ull, 0ull, 0ull};

#pragma unroll 4
    for (int k = 0; k < CC; k++) {
        u64 u2 = *(const u64*)&s_u[k * 64 + px];
        ulonglong2 wa = *(const ulonglong2*)&s_w2[k * 32 + o0];      // outs 0,1
        ulonglong2 wb = *(const ulonglong2*)&s_w2[k * 32 + o0 + 2];  // outs 2,3
        ffma2(acc[0], u2, wa.x);
        ffma2(acc[1], u2, wa.y);
        ffma2(acc[2], u2, wb.x);
        ffma2(acc[3], u2, wb.y);
    }

    float* op = g_phi + ((size_t)b * CC + half * 32 + o0) * 16384 + pb + px;
#pragma unroll
    for (int j = 0; j < 4; j++)
        *(u64*)(op + (size_t)j * 16384) = acc[j];
}

// ---------------------------------------------------------------------------
// K2: M maps v4. Block 512 = 16 warps: warp -> (dy-group of 4, channel-quarter
// of 16c); grid (256 rows, 2 dy-halves) -> 8192 warps. Shifted neighbors built
// by SHFL from the single center-row load (halves LDG wavefronts); lane 0/31
// zeroed to preserve the x>0 / x<124 window semantics. 4 channel partials
// combined via conflict-free pitch-29 smem.
// ---------------------------------------------------------------------------
__global__ void __launch_bounds__(512)
m_kernel() {
    __shared__ float s_part[12 * 32 * 29];     // [grp_local*3+chalf-1][lane][28+pad] 44.5KB
    int tid  = threadIdx.x;
    int lane = tid & 31;
    int wrp  = tid >> 5;                       // 0..15
    int grp_local = wrp >> 2;                  // 0..3
    int chalf     = wrp & 3;                   // channels chalf*16 .. +15
    int grp  = blockIdx.y * 4 + grp_local;     // 0..7; 7 idle
    int row  = blockIdx.x;                     // 0..255
    int b = row >> 7, y = row & 127;
    int dy = grp - 3;
    int x  = lane << 2;
    int ys = y + dy;
    bool live  = (grp < 7);
    bool rowok = live && ((unsigned)ys < (unsigned)HH);

    float acc[28];
#pragma unroll
    for (int i = 0; i < 28; i++) acc[i] = 0.f;

    if (live) {
        const float* pcb = g_phi + (size_t)(b * CC + chalf * 16) * 16384 + y  * WW + x;
        const float* psb = g_phi + (size_t)(b * CC + chalf * 16) * 16384 + ys * WW + x;
#pragma unroll 4
        for (int c = 0; c < 16; c++) {
            float4 ctr = *(const float4*)(pcb + (size_t)c * 16384);
            float4 w1 = make_float4(0.f, 0.f, 0.f, 0.f);
            if (rowok) w1 = *(const float4*)(psb + (size_t)c * 16384);
            // neighbors via shfl: w0 = left lane's w1 (x-4..x-1), w2 = right's
            float4 w0, w2;
            w0.x = __shfl_up_sync(0xffffffffu, w1.x, 1);
            w0.y = __shfl_up_sync(0xffffffffu, w1.y, 1);
            w0.z = __shfl_up_sync(0xffffffffu, w1.z, 1);
            w0.w = __shfl_up_sync(0xffffffffu, w1.w, 1);
            w2.x = __shfl_down_sync(0xffffffffu, w1.x, 1);
            w2.y = __shfl_down_sync(0xffffffffu, w1.y, 1);
            w2.z = __shfl_down_sync(0xffffffffu, w1.z, 1);
            w2.w = __shfl_down_sync(0xffffffffu, w1.w, 1);
            if (lane == 0)  w0 = make_float4(0.f, 0.f, 0.f, 0.f);  // x==0 edge
            if (lane == 31) w2 = make_float4(0.f, 0.f, 0.f, 0.f);  // x==124 edge
            float win[12] = {w0.x, w0.y, w0.z, w0.w,
                             w1.x, w1.y, w1.z, w1.w,
                             w2.x, w2.y, w2.z, w2.w};
            float ct[4] = {ctr.x, ctr.y, ctr.z, ctr.w};
#pragma unroll
            for (int d = 0; d < 7; d++)        // dx = d-3
#pragma unroll
                for (int j = 0; j < 4; j++)
                    acc[d * 4 + j] += ct[j] * win[1 + d + j];
        }
    }

    // combine the 4 channel-quarters
    if (live && chalf > 0) {
        float* sp = &s_part[((grp_local * 3 + chalf - 1) * 32 + lane) * 29];
#pragma unroll
        for (int i = 0; i < 28; i++) sp[i] = acc[i];
    }
    __syncthreads();
    if (live && chalf == 0) {
#pragma unroll
        for (int q = 0; q < 3; q++) {
            const float* sp = &s_part[((grp_local * 3 + q) * 32 + lane) * 29];
#pragma unroll
            for (int i = 0; i < 28; i++) acc[i] += sp[i];
        }
        float* mb = g_M + b * 16384 + y * WW + x;
#pragma unroll
        for (int d = 0; d < 7; d++)
            *(float4*)(mb + (size_t)(grp * 7 + d) * 32768) =
                make_float4(acc[d * 4], acc[d * 4 + 1], acc[d * 4 + 2], acc[d * 4 + 3]);
    }
}

// ---------------------------------------------------------------------------
// K3: boxsum + mask + softmax. grid (2 xb, 128 y, 2 b), block 512.
// Thread (px 0..63, dyg 0..7; dyg==7 idle in compute). Lanes = consecutive x
// -> coalesced M reads. Cross-dy softmax via tiny smem reduction (pitch 9).
// ---------------------------------------------------------------------------
__global__ void __launch_bounds__(512)
attn_kernel(float* __restrict__ out) {
    __shared__ float s_red[64 * 9];
    int t   = threadIdx.x;
    int px  = t & 63;
    int dyg = t >> 6;                          // 0..7
    int b = blockIdx.z, y = blockIdx.y, x = blockIdx.x * 64 + px;

    float sc[7];
    float lmax = -1e30f;
    if (dyg < 7) {
        int dy = dyg - 3;
#pragma unroll
        for (int d3 = 0; d3 < 7; d3++) {
            int dx = d3 - 3;
            float s = 0.f;
            const float* mb = g_M + (size_t)(dyg * 7 + d3) * 32768 + b * 16384;
#pragma unroll
            for (int ey = -1; ey <= 1; ey++) {
                int yy = y + ey;
                if ((unsigned)yy < (unsigned)HH) {
#pragma unroll
                    for (int ex = -1; ex <= 1; ex++) {
                        int xx = x + ex;
                        if ((unsigned)xx < (unsigned)WW) s += mb[yy * WW + xx];
                    }
                }
            }
            bool valid = ((unsigned)(y + dy) < (unsigned)HH) &&
                         ((unsigned)(x + dx) < (unsigned)WW);
            sc[d3] = valid ? s : 0.f;
            lmax = fmaxf(lmax, sc[d3]);
        }
    }
    s_red[px * 9 + dyg] = lmax;                // dyg==7 writes -1e30 (ignored)
    __syncthreads();

    float gmax = s_red[px * 9 + 0];
#pragma unroll
    for (int j = 1; j < 7; j++) gmax = fmaxf(gmax, s_red[px * 9 + j]);

    float e[7];
    float lsum = 0.f;
    if (dyg < 7) {
#pragma unroll
        for (int d3 = 0; d3 < 7; d3++) { e[d3] = __expf(sc[d3] - gmax); lsum += e[d3]; }
    }
    __syncthreads();                           // protect s_red before overwrite
    s_red[px * 9 + dyg] = lsum;                // dyg==7 writes 0 (lsum init, not read)
    __syncthreads();

    float gsum = 0.f;
#pragma unroll
    for (int j = 0; j < 7; j++) gsum += s_red[px * 9 + j];

    if (dyg < 7) {
        float inv = 1.0f / gsum;
        float* op = out + (size_t)(b * 16384 + y * WW + x) * 49 + dyg * 7;
#pragma unroll
        for (int d3 = 0; d3 < 7; d3++) op[d3] = e[d3] * inv;
    }
}

extern "C" void kernel_launch(void* const* d_in, const int* in_sizes, int n_in,
                              void* d_out, int out_size) {
    const float* u = (const float*)d_in[0];    // [2,64,128,128]
    const float* w = (const float*)d_in[1];    // [64,64]
    float* out = (float*)d_out;                // [2,128,128,1,49]

    phi_kernel<<<dim3(512, 2), 256>>>(u, w);
    m_kernel<<<dim3(256, 2), 512>>>();
    attn_kernel<<<dim3(2, 128, 2), 512>>>(out);
}

// round 17
// speedup vs baseline: 1.2883x; 1.2883x over previous
#include <cuda_runtime.h>

// SpatialWeightsEsDot on GB300.
//   phi = w_phi @ u (1x1 conv), layout [b][c][y][x]
//   M_{dy,dx}[b][y][x] = sum_c phi[b,c,y,x]*phi[b,c,y+dy,x+dx]  (zero outside image)
//   g_M stores Mh = horizontal 3-sum of M (boxsum's x-pass, edge-clamped)
//   score[p,d] = 1[p+d in image] * sum_{ey} Mh_d[y+ey, x]
//   out = softmax over the 49 offsets -> [2,128,128,1,49]

#define HH 128
#define WW 128
#define CC 64

__device__ float g_phi[2 * CC * HH * WW];     // [b][c][y][x]
__device__ float g_M[49 * 2 * HH * WW];       // Mh: [off][b][y][x]

typedef unsigned long long u64;

__device__ __forceinline__ void ffma2(u64& d, u64 a, u64 b) {
    asm("fma.rn.f32x2 %0, %1, %2, %3;" : "=l"(d) : "l"(a), "l"(b), "l"(d));
}
__device__ __forceinline__ u64 dup2(float v) {
    u64 d; asm("mov.b64 %0, {%1, %1};" : "=l"(d) : "f"(v)); return d;
}

// ---------------------------------------------------------------------------
// K1: phi v8 (measured best: 18.1us). Thread = 4 px x 4 outs, warp = 128
// contiguous px sharing one out-group (true broadcast w). Grid (256,2) x 256
// = 4096 warps. Per k: 2 LDS.128 + 4 dup-mov + 8 FFMA2 (2 B/MAC).
// ---------------------------------------------------------------------------
__global__ void __launch_bounds__(256)
phi_kernel(const float* __restrict__ u, const float* __restrict__ w) {
    __shared__ float s_u[CC * 128];            // [k][px] 32KB
    __shared__ float s_w[CC * 32];             // [k][o-in-half] 8KB
    int tid  = threadIdx.x;
    int p0   = blockIdx.x * 128;
    int b    = p0 >> 14;
    int pb   = p0 & 16383;
    int half = blockIdx.y;                     // outputs half*32 .. half*32+31

    for (int i = tid; i < CC * 32; i += 256) {
        int k = i >> 5, o = i & 31;
        s_w[i] = w[(half * 32 + o) * CC + k];
    }
    const float* ub = u + (size_t)b * CC * 16384 + pb;
    for (int i = tid; i < 2048; i += 256) {    // 64k x 32 float4
        int k = i >> 5, p4 = (i & 31) << 2;
        *(float4*)&s_u[k * 128 + p4] = *(const float4*)(ub + (size_t)k * 16384 + p4);
    }
    __syncthreads();

    int lane = tid & 31;
    int og   = tid >> 5;                       // warp id 0..7 -> 4 outs
    int px   = lane << 2;                      // 4 contiguous px per lane
    int o0   = og << 2;

    u64 acc[4][2];
#pragma unroll
    for (int j = 0; j < 4; j++) { acc[j][0] = 0ull; acc[j][1] = 0ull; }

#pragma unroll 4
    for (int k = 0; k < CC; k++) {
        ulonglong2 uv = *(const ulonglong2*)&s_u[k * 128 + px];   // px 0..3
        float4 wv = *(const float4*)&s_w[k * 32 + o0];            // broadcast
        u64 w0 = dup2(wv.x), w1 = dup2(wv.y), w2 = dup2(wv.z), w3 = dup2(wv.w);
        ffma2(acc[0][0], uv.x, w0); ffma2(acc[0][1], uv.y, w0);
        ffma2(acc[1][0], uv.x, w1); ffma2(acc[1][1], uv.y, w1);
        ffma2(acc[2][0], uv.x, w2); ffma2(acc[2][1], uv.y, w2);
        ffma2(acc[3][0], uv.x, w3); ffma2(acc[3][1], uv.y, w3);
    }

    float* op = g_phi + ((size_t)b * CC + half * 32 + o0) * 16384 + pb + px;
#pragma unroll
    for (int j = 0; j < 4; j++)
        *(ulonglong2*)(op + (size_t)j * 16384) = make_ulonglong2(acc[j][0], acc[j][1]);
}

// ---------------------------------------------------------------------------
// K2: M maps v5 = v4 + fused horizontal boxsum pass. Block 512 = 16 warps:
// warp -> (dy-group, channel-quarter of 16c); grid (256 rows, 2 dy-halves).
// Shifted row from single LDG + SHFL neighbors (lane 0/31 zeroed = x-window
// edges). chalf partials combined via pitch-29 smem; the finalizing warp
// 3-sums horizontally (2 SHFLs for cross-lane edges, zero-clamped = attn's
// 0<=xx<128 guard) and stores Mh.
// ---------------------------------------------------------------------------
__global__ void __launch_bounds__(512)
m_kernel() {
    __shared__ float s_part[12 * 32 * 29];     // 44.5KB
    int tid  = threadIdx.x;
    int lane = tid & 31;
    int wrp  = tid >> 5;                       // 0..15
    int grp_local = wrp >> 2;                  // 0..3
    int chalf     = wrp & 3;                   // channels chalf*16 .. +15
    int grp  = blockIdx.y * 4 + grp_local;     // 0..7; 7 idle
    int row  = blockIdx.x;                     // 0..255
    int b = row >> 7, y = row & 127;
    int dy = grp - 3;
    int x  = lane << 2;
    int ys = y + dy;
    bool live  = (grp < 7);
    bool rowok = live && ((unsigned)ys < (unsigned)HH);

    float acc[28];
#pragma unroll
    for (int i = 0; i < 28; i++) acc[i] = 0.f;

    if (live) {
        const float* pcb = g_phi + (size_t)(b * CC + chalf * 16) * 16384 + y  * WW + x;
        const float* psb = g_phi + (size_t)(b * CC + chalf * 16) * 16384 + ys * WW + x;
#pragma unroll 4
        for (int c = 0; c < 16; c++) {
            float4 ctr = *(const float4*)(pcb + (size_t)c * 16384);
            float4 w1 = make_float4(0.f, 0.f, 0.f, 0.f);
            if (rowok) w1 = *(const float4*)(psb + (size_t)c * 16384);
            float4 w0, w2;
            w0.x = __shfl_up_sync(0xffffffffu, w1.x, 1);
            w0.y = __shfl_up_sync(0xffffffffu, w1.y, 1);
            w0.z = __shfl_up_sync(0xffffffffu, w1.z, 1);
            w0.w = __shfl_up_sync(0xffffffffu, w1.w, 1);
            w2.x = __shfl_down_sync(0xffffffffu, w1.x, 1);
            w2.y = __shfl_down_sync(0xffffffffu, w1.y, 1);
            w2.z = __shfl_down_sync(0xffffffffu, w1.z, 1);
            w2.w = __shfl_down_sync(0xffffffffu, w1.w, 1);
            if (lane == 0)  w0 = make_float4(0.f, 0.f, 0.f, 0.f);  // x==0 edge
            if (lane == 31) w2 = make_float4(0.f, 0.f, 0.f, 0.f);  // x==124 edge
            float win[12] = {w0.x, w0.y, w0.z, w0.w,
                             w1.x, w1.y, w1.z, w1.w,
                             w2.x, w2.y, w2.z, w2.w};
            float ct[4] = {ctr.x, ctr.y, ctr.z, ctr.w};
#pragma unroll
            for (int d = 0; d < 7; d++)        // dx = d-3
#pragma unroll
                for (int j = 0; j < 4; j++)
                    acc[d * 4 + j] += ct[j] * win[1 + d + j];
        }
    }

    if (live && chalf > 0) {
        float* sp = &s_part[((grp_local * 3 + chalf - 1) * 32 + lane) * 29];
#pragma unroll
        for (int i = 0; i < 28; i++) sp[i] = acc[i];
    }
    __syncthreads();
    if (live && chalf == 0) {
#pragma unroll
        for (int q = 0; q < 3; q++) {
            const float* sp = &s_part[((grp_local * 3 + q) * 32 + lane) * 29];
#pragma unroll
            for (int i = 0; i < 28; i++) acc[i] += sp[i];
        }
        // horizontal 3-sum (boxsum x-pass): Mh[x] = M[x-1]+M[x]+M[x+1], 0 outside
        float* mb = g_M + b * 16384 + y * WW + x;
#pragma unroll
        for (int d = 0; d < 7; d++) {
            float a0 = acc[d * 4], a1 = acc[d * 4 + 1];
            float a2 = acc[d * 4 + 2], a3 = acc[d * 4 + 3];
            float left  = __shfl_up_sync(0xffffffffu, a3, 1);    // M[x-1]
            float right = __shfl_down_sync(0xffffffffu, a0, 1);  // M[x+4]
            if (lane == 0)  left  = 0.f;                         // x==0 edge
            if (lane == 31) right = 0.f;                         // x==127 edge
            *(float4*)(mb + (size_t)(grp * 7 + d) * 32768) =
                make_float4(left + a0 + a1, a0 + a1 + a2, a1 + a2 + a3, a2 + a3 + right);
        }
    }
}

// ---------------------------------------------------------------------------
// K3: attn v2 -- vertical boxsum pass + mask + softmax. grid (2 xb, 128 y,
// 2 b), block 512. Thread (px 0..63, dyg 0..7). 3 row-loads per offset
// (Mh pre-summed horizontally) instead of 9 point-loads.
// ---------------------------------------------------------------------------
__global__ void __launch_bounds__(512)
attn_kernel(float* __restrict__ out) {
    __shared__ float s_red[64 * 9];
    int t   = threadIdx.x;
    int px  = t & 63;
    int dyg = t >> 6;                          // 0..7
    int b = blockIdx.z, y = blockIdx.y, x = blockIdx.x * 64 + px;

    float sc[7];
    float lmax = -1e30f;
    if (dyg < 7) {
        int dy = dyg - 3;
#pragma unroll
        for (int d3 = 0; d3 < 7; d3++) {
            int dx = d3 - 3;
            const float* mb = g_M + (size_t)(dyg * 7 + d3) * 32768 + b * 16384 + x;
            float s = mb[y * WW];
            if (y > 0)      s += mb[(y - 1) * WW];
            if (y < HH - 1) s += mb[(y + 1) * WW];
            bool valid = ((unsigned)(y + dy) < (unsigned)HH) &&
                         ((unsigned)(x + dx) < (unsigned)WW);
            sc[d3] = valid ? s : 0.f;
            lmax = fmaxf(lmax, sc[d3]);
        }
    }
    s_red[px * 9 + dyg] = lmax;                // dyg==7 writes -1e30 (ignored)
    __syncthreads();

    float gmax = s_red[px * 9 + 0];
#pragma unroll
    for (int j = 1; j < 7; j++) gmax = fmaxf(gmax, s_red[px * 9 + j]);

    float e[7];
    float lsum = 0.f;
    if (dyg < 7) {
#pragma unroll
        for (int d3 = 0; d3 < 7; d3++) { e[d3] = __expf(sc[d3] - gmax); lsum += e[d3]; }
    }
    __syncthreads();                           // protect s_red before overwrite
    s_red[px * 9 + dyg] = lsum;                // dyg==7 writes 0 (lsum init, not read)
    __syncthreads();

    float gsum = 0.f;
#pragma unroll
    for (int j = 0; j < 7; j++) gsum += s_red[px * 9 + j];

    if (dyg < 7) {
        float inv = 1.0f / gsum;
        float* op = out + (size_t)(b * 16384 + y * WW + x) * 49 + dyg * 7;
#pragma unroll
        for (int d3 = 0; d3 < 7; d3++) op[d3] = e[d3] * inv;
    }
}

extern "C" void kernel_launch(void* const* d_in, const int* in_sizes, int n_in,
                              void* d_out, int out_size) {
    const float* u = (const float*)d_in[0];    // [2,64,128,128]
    const float* w = (const float*)d_in[1];    // [64,64]
    float* out = (float*)d_out;                // [2,128,128,1,49]

    phi_kernel<<<dim3(256, 2), 256>>>(u, w);
    m_kernel<<<dim3(256, 2), 512>>>();
    attn_kernel<<<dim3(2, 128, 2), 512>>>(out);
}